// round 13
// baseline (speedup 1.0000x reference)
#include <cuda_runtime.h>
#include <cuda_bf16.h>
#include <cstdint>

#define BB 8
#define TT 2304
#define CC 512
#define HS 48
#define HH 64
#define NN 8
#define MM (BB*TT)
#define BTC (MM*CC)
#define NCHUNK 24
#define CLEN 96          // TT / NCHUNK
#define NUNIT 1024       // 2 * BB * HH
#define TP 32            // positions per fused_dp2 block

// ---------------- scratch (device globals) ----------------
__device__ float g_xx[2*BTC];
__device__ float g_r [2*BTC];
__device__ float g_k [2*BTC];
__device__ float g_v [2*BTC];
__device__ float g_d [2*BTC];
__device__ float g_y [2*BTC];
__device__ float g_coef[25*CC];      // merged 5x5 stencil per channel, [tap][c]
// bf16 hi/lo planes: A variants 0..5 = dir*3 + {r,k,v}; 6 = layernormed
__device__ uint16_t g_Ahi[7*(size_t)BTC];
__device__ uint16_t g_Alo[7*(size_t)BTC];
__device__ uint16_t g_Whi[4*CC*CC];   // 0=Wr 1=Wk 2=Wv 3=Wo
__device__ uint16_t g_Wlo[4*CC*CC];
// chunked scan scratch
__device__ float g_M [NUNIT*NCHUNK*64];
__device__ float g_P [NUNIT*NCHUNK*8];
__device__ float g_S0[NUNIT*NCHUNK*64];

__device__ __forceinline__ float4 ld4(const float* p) { return *(const float4*)p; }

__device__ __forceinline__ void bfsplit4(float4 v, uint2& hi, uint2& lo) {
    __nv_bfloat16 hx = __float2bfloat16(v.x);
    __nv_bfloat16 hy = __float2bfloat16(v.y);
    __nv_bfloat16 hz = __float2bfloat16(v.z);
    __nv_bfloat16 hw = __float2bfloat16(v.w);
    float rx = v.x - __bfloat162float(hx);
    float ry = v.y - __bfloat162float(hy);
    float rz = v.z - __bfloat162float(hz);
    float rw = v.w - __bfloat162float(hw);
    __nv_bfloat16 lx = __float2bfloat16(rx);
    __nv_bfloat16 ly = __float2bfloat16(ry);
    __nv_bfloat16 lz = __float2bfloat16(rz);
    __nv_bfloat16 lw = __float2bfloat16(rw);
    hi.x = ((uint32_t)__bfloat16_as_ushort(hy) << 16) | __bfloat16_as_ushort(hx);
    hi.y = ((uint32_t)__bfloat16_as_ushort(hw) << 16) | __bfloat16_as_ushort(hz);
    lo.x = ((uint32_t)__bfloat16_as_ushort(ly) << 16) | __bfloat16_as_ushort(lx);
    lo.y = ((uint32_t)__bfloat16_as_ushort(lw) << 16) | __bfloat16_as_ushort(lz);
}

// ---------------- merged stencil coefficients ----------------
__global__ void prep_coef_kernel(const float* __restrict__ c1,
                                 const float* __restrict__ c3,
                                 const float* __restrict__ c5,
                                 const float* __restrict__ alpha)
{
    const int c = threadIdx.x;   // 512
    const float a0 = alpha[0], a1 = alpha[1], a2 = alpha[2], a3 = alpha[3];
    #pragma unroll
    for (int i = 0; i < 5; ++i) {
        #pragma unroll
        for (int j = 0; j < 5; ++j) {
            float w = a3 * c5[c*25 + i*5 + j];
            if (i >= 1 && i <= 3 && j >= 1 && j <= 3)
                w += a2 * c3[c*9 + (i-1)*3 + (j-1)];
            if (i == 2 && j == 2)
                w += a1 * c1[c] + a0 - 1.0f;    // -1: xx = sh - x
            g_coef[(i*5+j)*CC + c] = w;
        }
    }
}

// ---------------- conv shift v2: register-window stencil ----------------
__global__ __launch_bounds__(256)
void conv_shift2_kernel(const float* __restrict__ x)
{
    const int u   = blockIdx.x;
    const int b   = blockIdx.y;
    const int dir = blockIdx.z;
    const int c0  = (threadIdx.x & 127) * 4;
    const int qh  = threadIdx.x >> 7;
    const float* xb = x + (size_t)b*TT*CC;
    float* xxb = g_xx + (size_t)dir*BTC + (size_t)b*TT*CC;

    for (int ch = 0; ch < 3; ++ch) {
        const int q0 = qh*24 + ch*8;
        float4 acc[8];
        #pragma unroll
        for (int qi = 0; qi < 8; ++qi) acc[qi] = make_float4(0.f, 0.f, 0.f, 0.f);

        #pragma unroll
        for (int i = 0; i < 5; ++i) {
            const int uu = u + i - 2;
            if (uu < 0 || uu >= HS) continue;
            float4 xwin[12];
            #pragma unroll
            for (int t = 0; t < 12; ++t) {
                const int qq = q0 - 2 + t;
                if (qq >= 0 && qq < HS) {
                    const int idx = dir ? (qq*HS + uu) : (uu*HS + qq);
                    xwin[t] = ld4(xb + (size_t)idx*CC + c0);
                } else {
                    xwin[t] = make_float4(0.f, 0.f, 0.f, 0.f);
                }
            }
            #pragma unroll
            for (int j = 0; j < 5; ++j) {
                const float4 cf = ld4(g_coef + (i*5+j)*CC + c0);
                #pragma unroll
                for (int qi = 0; qi < 8; ++qi) {
                    const float4 xv = xwin[qi + j];
                    acc[qi].x = fmaf(cf.x, xv.x, acc[qi].x);
                    acc[qi].y = fmaf(cf.y, xv.y, acc[qi].y);
                    acc[qi].z = fmaf(cf.z, xv.z, acc[qi].z);
                    acc[qi].w = fmaf(cf.w, xv.w, acc[qi].w);
                }
            }
        }
        #pragma unroll
        for (int qi = 0; qi < 8; ++qi)
            *(float4*)(xxb + (size_t)(u*HS + q0 + qi)*CC + c0) = acc[qi];
    }
}

// ---------------- fused decay + bf16 plane prep, v2.1 ----------------
__global__ __launch_bounds__(256)
void fused_dp2_kernel(const float* __restrict__ x,
                      const float* __restrict__ maa_w,
                      const float* __restrict__ maar,
                      const float* __restrict__ maak,
                      const float* __restrict__ maav,
                      const float* __restrict__ tdec,
                      const float* __restrict__ w1,   // [C][16]
                      const float* __restrict__ w2)   // [16][C]
{
    __shared__ float w1s[16*CC];     // w1 transposed [j][c]; reused for w2 [j][c]
    __shared__ float maas[4*CC];     // r,k,v,w
    __shared__ float Hs[TP][16];

    const int tid = threadIdx.x;
    const int t0  = blockIdx.x * TP;
    const int b   = blockIdx.y;
    const int dir = blockIdx.z;

    for (int idx = tid; idx < 16*CC; idx += 256) {
        const int c = idx >> 4, j = idx & 15;
        w1s[j*CC + c] = w1[c*16 + j];
    }
    if (tid < 128) {
        ((float4*)maas)[tid]           = ld4(maar + tid*4);
        ((float4*)(maas + CC))[tid]    = ld4(maak + tid*4);
        ((float4*)(maas + 2*CC))[tid]  = ld4(maav + tid*4);
        ((float4*)(maas + 3*CC))[tid]  = ld4(maa_w + tid*4);
    }
    __syncthreads();

    const int p = tid >> 3;          // 0..31 position
    const int s = tid & 7;           // 0..7 channel slice
    const int t = t0 + p;
    const int m = b*TT + t;
    const int row = dir ? (b*TT + (t % HS)*HS + (t / HS)) : m;
    const size_t xxbase = (size_t)dir*BTC + (size_t)m*CC;
    const size_t u2base = (size_t)m*128;

    float h[16];
    #pragma unroll
    for (int j = 0; j < 16; ++j) h[j] = 0.0f;

    #pragma unroll 4
    for (int i = 0; i < 16; ++i) {
        const int c = (i*8 + s)*4;
        const float4 xv = ld4(x + (size_t)row*CC + c);
        const float4 xx = ld4(g_xx + xxbase + c);

        #pragma unroll
        for (int v = 0; v < 3; ++v) {
            const float4 mv = ld4(maas + v*CC + c);
            float4 a;
            a.x = fmaf(xx.x, mv.x, xv.x); a.y = fmaf(xx.y, mv.y, xv.y);
            a.z = fmaf(xx.z, mv.z, xv.z); a.w = fmaf(xx.w, mv.w, xv.w);
            uint2 hi, lo; bfsplit4(a, hi, lo);
            const size_t vb = (size_t)(dir*3 + v) * BTC;
            ((uint2*)(g_Ahi + vb))[u2base + c/4] = hi;
            ((uint2*)(g_Alo + vb))[u2base + c/4] = lo;
        }

        const float4 mw = ld4(maas + 3*CC + c);
        const float v0 = fmaf(xx.x, mw.x, xv.x);
        const float v1 = fmaf(xx.y, mw.y, xv.y);
        const float v2 = fmaf(xx.z, mw.z, xv.z);
        const float v3 = fmaf(xx.w, mw.w, xv.w);
        #pragma unroll
        for (int j = 0; j < 16; ++j) {
            const float4 w4 = *(const float4*)(w1s + j*CC + c);
            h[j] = fmaf(v0, w4.x, h[j]);
            h[j] = fmaf(v1, w4.y, h[j]);
            h[j] = fmaf(v2, w4.z, h[j]);
            h[j] = fmaf(v3, w4.w, h[j]);
        }
    }

    #pragma unroll
    for (int j = 0; j < 16; ++j) {
        h[j] += __shfl_xor_sync(0xffffffffu, h[j], 1);
        h[j] += __shfl_xor_sync(0xffffffffu, h[j], 2);
        h[j] += __shfl_xor_sync(0xffffffffu, h[j], 4);
    }
    if (s == 0) {
        #pragma unroll
        for (int j = 0; j < 16; ++j) Hs[p][j] = tanhf(h[j]);
    }
    __syncthreads();

    for (int idx4 = tid; idx4 < 16*CC/4; idx4 += 256)
        ((float4*)w1s)[idx4] = ((const float4*)w2)[idx4];
    __syncthreads();

    const int c0 = tid*2;
    float w2a[16], w2b[16];
    #pragma unroll
    for (int j = 0; j < 16; ++j) { w2a[j] = w1s[j*CC + c0]; w2b[j] = w1s[j*CC + c0 + 1]; }
    const float td0 = tdec[c0], td1 = tdec[c0+1];
    float* dbase = g_d + (size_t)dir*BTC + (size_t)(b*TT + t0)*CC + c0;
    #pragma unroll 4
    for (int pp = 0; pp < TP; ++pp) {
        float a0 = td0, a1 = td1;
        #pragma unroll
        for (int j = 0; j < 16; ++j) {
            const float hj = Hs[pp][j];
            a0 = fmaf(hj, w2a[j], a0);
            a1 = fmaf(hj, w2b[j], a1);
        }
        *(float2*)(dbase + (size_t)pp*CC) = make_float2(expf(-expf(a0)), expf(-expf(a1)));
    }
}

// ---------------- prep: W -> bf16 hi/lo planes (8 ch/thread) ----------------
__global__ void prep_w_kernel(const float* __restrict__ Wr, const float* __restrict__ Wk,
                              const float* __restrict__ Wv, const float* __restrict__ Wo)
{
    const int idx = blockIdx.x*256 + threadIdx.x;       // over 4*CC*CC/8
    const int w = idx >> 15;                             // CC*CC/8 = 32768
    const int r = idx & 32767;
    const float* W = (w==0) ? Wr : (w==1) ? Wk : (w==2) ? Wv : Wo;
    const float4 va = ld4(W + (size_t)r*8);
    const float4 vb = ld4(W + (size_t)r*8 + 4);
    uint2 ha, la, hb, lb;
    bfsplit4(va, ha, la);
    bfsplit4(vb, hb, lb);
    ((uint4*)(g_Whi + (size_t)w*CC*CC))[r] = make_uint4(ha.x, ha.y, hb.x, hb.y);
    ((uint4*)(g_Wlo + (size_t)w*CC*CC))[r] = make_uint4(la.x, la.y, lb.x, lb.y);
}

// ---------------- bf16-split tensor-core GEMM, 128x256 tile, 2-stage static (round-10 cfg) ----------------
// per stage: Ahi 4KB | Alo 4KB | Bhi 8KB | Blo 8KB = 24KB; 2 stages = 48KB
// rkv_mode: blockIdx.z selects variant: a_sel=z, w_sel=out_sel=z%3, dir=z/3
#define ST3_B 24576
#define O_ALO 4096
#define O_BHI 8192
#define O_BLO 16384

__device__ __forceinline__ void cp16(uint32_t dst, const void* src) {
    asm volatile("cp.async.cg.shared.global [%0], [%1], 16;\n" :: "r"(dst), "l"(src));
}
__device__ __forceinline__ void ldsm4(uint32_t* r, uint32_t a) {
    asm volatile("ldmatrix.sync.aligned.m8n8.x4.shared.b16 {%0,%1,%2,%3}, [%4];"
        : "=r"(r[0]), "=r"(r[1]), "=r"(r[2]), "=r"(r[3]) : "r"(a));
}

__global__ __launch_bounds__(256)
void gemm_bf16_kernel(float* __restrict__ Out_ext, int rkv_mode)
{
    __shared__ uint32_t sm[2*ST3_B/4];   // 48KB

    const int tid = threadIdx.x;
    const int bn = blockIdx.x * 256;
    const int bm = blockIdx.y * 128;

    int a_sel, w_sel, out_sel, dir;
    if (rkv_mode) {
        const int z = blockIdx.z;
        dir = z / 3;
        w_sel = z - dir*3;       // z % 3
        out_sel = w_sel;
        a_sel = z;               // dir*3 + variant
    } else {
        a_sel = 6; w_sel = 3; out_sel = 3; dir = 0;
    }

    const uint16_t* Ah = g_Ahi + (size_t)a_sel*BTC;
    const uint16_t* Al = g_Alo + (size_t)a_sel*BTC;
    const uint16_t* Bh = g_Whi + (size_t)w_sel*CC*CC;
    const uint16_t* Bl = g_Wlo + (size_t)w_sel*CC*CC;
    float* Out;
    switch (out_sel) {
        case 0: Out = g_r + (size_t)dir*BTC; break;
        case 1: Out = g_k + (size_t)dir*BTC; break;
        case 2: Out = g_v + (size_t)dir*BTC; break;
        default: Out = Out_ext; break;
    }

    // ---- staging geometry ----
    const int rowA  = tid >> 1;                 // 0..127
    const int halfA = tid & 1;
    const int hswA  = halfA ^ ((rowA >> 2) & 1);
    const uint16_t* pa_h = Ah + (size_t)(bm + rowA)*CC + halfA*8;
    const uint16_t* pa_l = Al + (size_t)(bm + rowA)*CC + halfA*8;
    const uint32_t smbase = (uint32_t)__cvta_generic_to_shared(&sm[0]);
    const uint32_t doffA = (uint32_t)(rowA*32 + hswA*16);
    // B: 256 rows -> 2 chunks/thread/plane
    const int rowB2 = rowA + 128;
    const int hswB2 = halfA ^ ((rowB2 >> 2) & 1);
    const uint16_t* pb_h0 = Bh + (size_t)(bn + rowA)*CC + halfA*8;
    const uint16_t* pb_l0 = Bl + (size_t)(bn + rowA)*CC + halfA*8;
    const uint16_t* pb_h1 = Bh + (size_t)(bn + rowB2)*CC + halfA*8;
    const uint16_t* pb_l1 = Bl + (size_t)(bn + rowB2)*CC + halfA*8;
    const uint32_t doffB0 = doffA;
    const uint32_t doffB1 = (uint32_t)(rowB2*32 + hswB2*16);

    const int lane = tid & 31;
    const int grp  = lane >> 2;
    const int qid  = lane & 3;
    const int wid  = tid >> 5;
    const int wm   = wid >> 2;      // 0..1 -> 64 M rows
    const int wn   = wid & 3;       // 0..3 -> 64 N cols

    const int selA = lane >> 3;
    const int rA   = wm*64 + ((selA & 1) << 3) + (lane & 7);
    const int hA   = (selA >> 1) ^ ((rA >> 2) & 1);
    const uint32_t offA = (uint32_t)(rA*32 + hA*16);
    const int rB0  = wn*64 + ((lane >> 4) << 3) + (lane & 7);
    const int hB4  = ((lane >> 3) & 1) ^ ((rB0 >> 2) & 1);
    const uint32_t offB4 = (uint32_t)(rB0*32 + hB4*16);

    float c[4][8][4];
    #pragma unroll
    for (int mt = 0; mt < 4; ++mt)
        #pragma unroll
        for (int nt = 0; nt < 8; ++nt)
            #pragma unroll
            for (int e = 0; e < 4; ++e) c[mt][nt][e] = 0.0f;

    // prologue: prefetch ktiles 0,1 into stages 0,1
    #pragma unroll
    for (int kt = 0; kt < 2; ++kt) {
        const uint32_t d = smbase + kt*ST3_B;
        const int off = kt*16;
        cp16(d + doffA, pa_h + off);
        cp16(d + O_ALO + doffA, pa_l + off);
        cp16(d + O_BHI + doffB0, pb_h0 + off);
        cp16(d + O_BHI + doffB1, pb_h1 + off);
        cp16(d + O_BLO + doffB0, pb_l0 + off);
        cp16(d + O_BLO + doffB1, pb_l1 + off);
        asm volatile("cp.async.commit_group;\n");
    }

    for (int kt = 0; kt < 32; ++kt) {
        const int p = kt & 1;
        asm volatile("cp.async.wait_group 1;\n");
        __syncthreads();

        const uint32_t sb = smbase + p*ST3_B;
        uint32_t ah[4][4], al[4][4], bh[8][2], bl[8][2];
        #pragma unroll
        for (int mt = 0; mt < 4; ++mt) ldsm4(ah[mt], sb + mt*512 + offA);
        #pragma unroll
        for (int mt = 0; mt < 4; ++mt) ldsm4(al[mt], sb + O_ALO + mt*512 + offA);
        #pragma unroll
        for (int np = 0; np < 4; ++np) {
            uint32_t btmp[4];
            ldsm4(btmp, sb + O_BHI + np*512 + offB4);
            bh[2*np][0] = btmp[0]; bh[2*np][1] = btmp[1];
            bh[2*np+1][0] = btmp[2]; bh[2*np+1][1] = btmp[3];
            ldsm4(btmp, sb + O_BLO + np*512 + offB4);
            bl[2*np][0] = btmp[0]; bl[2*np][1] = btmp[1];
            bl[2*np+1][0] = btmp[2]; bl[2*np+1][1] = btmp[3];
        }

        #pragma unroll
        for (int mt = 0; mt < 4; ++mt) {
            #pragma unroll
            for (int nt = 0; nt < 8; ++nt) {
                asm volatile(
                    "mma.sync.aligned.m16n8k16.row.col.f32.bf16.bf16.f32 "
                    "{%0,%1,%2,%3}, {%4,%5,%6,%7}, {%8,%9}, {%0,%1,%2,%3};"
                    : "+f"(c[mt][nt][0]), "+f"(c[mt][nt][1]),
                      "+f"(c[mt][nt][2]), "+f"(c[mt][nt][3])
                    : "r"(ah[mt][0]), "r"(ah[mt][1]), "r"(ah[mt][2]), "r"(ah[mt][3]),
                      "r"(bh[nt][0]), "r"(bh[nt][1]));
                asm volatile(
                    "mma.sync.aligned.m16n8k16.row.col.f32.bf16.bf16.f32 "
                    "{%0,%1,%2,%3}, {%4,%5,%6,%7}, {%8,%9}, {%0,%1,%2,%3};"
                    : "+f"(c[mt][nt][0]), "+f"(c[mt][nt][1]),
                      "+f"(c[mt][nt][2]), "+f"(c[mt][nt][3])
                    : "r"(al[mt][0]), "r"(al[mt][1]), "r"(al[mt][2]), "r"(al[mt][3]),
                      "r"(bh[nt][0]), "r"(bh[nt][1]));
                asm volatile(
                    "mma.sync.aligned.m16n8k16.row.col.f32.bf16.bf16.f32 "
                    "{%0,%1,%2,%3}, {%4,%5,%6,%7}, {%8,%9}, {%0,%1,%2,%3};"
                    : "+f"(c[mt][nt][0]), "+f"(c[mt][nt][1]),
                      "+f"(c[mt][nt][2]), "+f"(c[mt][nt][3])
                    : "r"(ah[mt][0]), "r"(ah[mt][1]), "r"(ah[mt][2]), "r"(ah[mt][3]),
                      "r"(bl[nt][0]), "r"(bl[nt][1]));
            }
        }

        __syncthreads();
        if (kt + 2 < 32) {
            const uint32_t d = smbase + p*ST3_B;
            const int off = (kt+2)*16;
            cp16(d + doffA, pa_h + off);
            cp16(d + O_ALO + doffA, pa_l + off);
            cp16(d + O_BHI + doffB0, pb_h0 + off);
            cp16(d + O_BHI + doffB1, pb_h1 + off);
            cp16(d + O_BLO + doffB0, pb_l0 + off);
            cp16(d + O_BLO + doffB1, pb_l1 + off);
        }
        asm volatile("cp.async.commit_group;\n");
    }

    // epilogue
    #pragma unroll
    for (int mt = 0; mt < 4; ++mt) {
        const int rrow = bm + wm*64 + mt*16 + grp;
        #pragma unroll
        for (int nt = 0; nt < 8; ++nt) {
            const int col = bn + wn*64 + nt*8 + qid*2;
            *(float2*)(Out + (size_t)rrow*CC + col)     = make_float2(c[mt][nt][0], c[mt][nt][1]);
            *(float2*)(Out + (size_t)(rrow+8)*CC + col) = make_float2(c[mt][nt][2], c[mt][nt][3]);
        }
    }
}

// ---------------- WKV6 chunked scan ----------------
__global__ void wkv_pass1_kernel()
{
    const int gt = blockIdx.x*128 + threadIdx.x;
    const int s = gt & 15;
    const int j = s & 7, p = s >> 3;
    const int i0 = p*4;
    const int ucid = gt >> 4;
    const int cch = ucid % NCHUNK;
    const int unit = ucid / NCHUNK;
    const int h = unit & 63, b = (unit >> 6) & 7, dir = unit >> 9;

    const size_t base = (size_t)dir*BTC + (size_t)(b*TT + cch*CLEN)*CC + h*NN;
    const float* kk = g_k + base;
    const float* vv = g_v + base;
    const float* dd = g_d + base;

    float S0=0.f,S1=0.f,S2=0.f,S3=0.f, P0=1.f,P1=1.f,P2=1.f,P3=1.f;
    int off = 0;
    #pragma unroll 4
    for (int t = 0; t < CLEN; ++t, off += CC) {
        const float4 k4 = ld4(kk + off + i0);
        const float4 d4 = ld4(dd + off + i0);
        const float v = vv[off + j];
        S0 = fmaf(d4.x, S0, k4.x*v); P0 *= d4.x;
        S1 = fmaf(d4.y, S1, k4.y*v); P1 *= d4.y;
        S2 = fmaf(d4.z, S2, k4.z*v); P2 *= d4.z;
        S3 = fmaf(d4.w, S3, k4.w*v); P3 *= d4.w;
    }
    float* Mp = g_M + (size_t)ucid*64;
    Mp[(i0+0)*8 + j] = S0;
    Mp[(i0+1)*8 + j] = S1;
    Mp[(i0+2)*8 + j] = S2;
    Mp[(i0+3)*8 + j] = S3;
    if (j == 0) {
        float* Pp = g_P + (size_t)ucid*8;
        Pp[i0+0] = P0; Pp[i0+1] = P1; Pp[i0+2] = P2; Pp[i0+3] = P3;
    }
}

__global__ void wkv_pass2_kernel()
{
    const int gt = blockIdx.x*128 + threadIdx.x;   // 16384 threads
    const int s = gt & 15;
    const int j = s & 7, p = s >> 3;
    const int i0 = p*4;
    const int unit = gt >> 4;

    float S0=0.f,S1=0.f,S2=0.f,S3=0.f;
    for (int cch = 0; cch < NCHUNK; ++cch) {
        const size_t uc = (size_t)unit*NCHUNK + cch;
        float* Sp = g_S0 + uc*64;
        Sp[(i0+0)*8 + j] = S0;
        Sp[(i0+1)*8 + j] = S1;
        Sp[(i0+2)*8 + j] = S2;
        Sp[(i0+3)*8 + j] = S3;
        const float* Pp = g_P + uc*8;
        const float* Mp = g_M + uc*64;
        S0 = fmaf(Pp[i0+0], S0, Mp[(i0+0)*8 + j]);
        S1 = fmaf(Pp[i0+1], S1, Mp[(i0+1)*8 + j]);
        S2 = fmaf(Pp[i0+2], S2, Mp[(i0+2)*8 + j]);
        S3 = fmaf(Pp[i0+3], S3, Mp[(i0+3)*8 + j]);
    }
}

__global__ void wkv_pass3_kernel(const float* __restrict__ u)
{
    const int gt = blockIdx.x*128 + threadIdx.x;
    const int s = gt & 15;
    const int j = s & 7, p = s >> 3;
    const int i0 = p*4;
    const int ucid = gt >> 4;
    const int cch = ucid % NCHUNK;
    const int unit = ucid / NCHUNK;
    const int h = unit & 63, b = (unit >> 6) & 7, dir = unit >> 9;

    const float4 uu = ld4(u + h*NN + i0);
    const size_t base = (size_t)dir*BTC + (size_t)(b*TT + cch*CLEN)*CC + h*NN;
    const float* rr = g_r + base;
    const float* kk = g_k + base;
    const float* vv = g_v + base;
    const float* dd = g_d + base;
    float* yy = g_y + base;

    const float* Sp = g_S0 + (size_t)ucid*64;
    float S0 = Sp[(i0+0)*8 + j];
    float S1 = Sp[(i0+1)*8 + j];
    float S2 = Sp[(i0+2)*8 + j];
    float S3 = Sp[(i0+3)*8 + j];

    int off = 0;
    #pragma unroll 2
    for (int t = 0; t < CLEN; ++t, off += CC) {
        const float4 r4 = ld4(rr + off + i0);
        const float4 k4 = ld4(kk + off + i0);
        const float4 d4 = ld4(dd + off + i0);
        const float v = vv[off + j];
        float y = 0.f, kv, tt;
        kv = k4.x*v; tt = fmaf(uu.x, kv, S0); y = fmaf(r4.x, tt, y); S0 = fmaf(d4.x, S0, kv);
        kv = k4.y*v; tt = fmaf(uu.y, kv, S1); y = fmaf(r4.y, tt, y); S1 = fmaf(d4.y, S1, kv);
        kv = k4.z*v; tt = fmaf(uu.z, kv, S2); y = fmaf(r4.z, tt, y); S2 = fmaf(d4.z, S2, kv);
        kv = k4.w*v; tt = fmaf(uu.w, kv, S3); y = fmaf(r4.w, tt, y); S3 = fmaf(d4.w, S3, kv);
        y += __shfl_xor_sync(0xffffffffu, y, 8);
        if (p == 0) yy[off + j] = y;
    }
}

// ---------------- combine directions + layernorm -> bf16 hi/lo planes (slot 6) ----------------
__global__ void combine_ln_kernel(const float* __restrict__ lng,
                                  const float* __restrict__ lnb)
{
    const int t = blockIdx.x, b = blockIdx.y;
    const int tid = threadIdx.x;   // 128
    const int c0 = tid*4;
    const int y = t / HS, xq = t % HS;
    const int tcol = xq*HS + y;
    const int m = b*TT + t;
    const float* yr = g_y + (size_t)m*CC;
    const float* yc = g_y + (size_t)BTC + (size_t)(b*TT + tcol)*CC;

    const float4 va = ld4(yr + c0);
    const float4 vb = ld4(yc + c0);
    float4 o;
    o.x = 0.5f*(va.x + vb.x); o.y = 0.5f*(va.y + vb.y);
    o.z = 0.5f*(va.z + vb.z); o.w = 0.5f*(va.w + vb.w);
    float s  = o.x + o.y + o.z + o.w;
    float sq = o.x*o.x + o.y*o.y + o.z*o.z + o.w*o.w;
    #pragma unroll
    for (int off = 16; off > 0; off >>= 1) {
        s  += __shfl_xor_sync(0xffffffffu, s,  off);
        sq += __shfl_xor_sync(0xffffffffu, sq, off);
    }
    __shared__ float ss[4], sqs[4];
    if ((tid & 31) == 0) { ss[tid >> 5] = s; sqs[tid >> 5] = sq; }
    __syncthreads();
    s  = ss[0] + ss[1] + ss[2] + ss[3];
    sq = sqs[0] + sqs[1] + sqs[2] + sqs[3];
    const float mu = s * (1.0f/CC);
    const float var = sq * (1.0f/CC) - mu*mu;
    const float rstd = rsqrtf(var + 1e-5f);

    const float4 g4 = ld4(lng + c0);
    const float4 b4 = ld4(lnb + c0);
    float4 res;
    res.x = (o.x - mu)*rstd*g4.x + b4.x;
    res.y = (o.y - mu)*rstd*g4.y + b4.y;
    res.z = (o.z - mu)*rstd*g4.z + b4.z;
    res.w = (o.w - mu)*rstd*g4.w + b4.w;
    uint2 hi, lo;
    bfsplit4(res, hi, lo);
    const size_t u2idx = (size_t)m*128 + tid;
    ((uint2*)(g_Ahi + (size_t)6*BTC))[u2idx] = hi;
    ((uint2*)(g_Alo + (size_t)6*BTC))[u2idx] = lo;
}

// ---------------- launch ----------------
extern "C" void kernel_launch(void* const* d_in, const int* in_sizes, int n_in,
                              void* d_out, int out_size)
{
    (void)in_sizes; (void)n_in; (void)out_size;
    const float* x     = (const float*)d_in[0];
    const float* c1    = (const float*)d_in[3];
    const float* c3    = (const float*)d_in[4];
    const float* c5    = (const float*)d_in[5];
    const float* alpha = (const float*)d_in[6];
    const float* maa_w = (const float*)d_in[7];
    const float* maa_k = (const float*)d_in[8];
    const float* maa_v = (const float*)d_in[9];
    const float* maa_r = (const float*)d_in[10];
    const float* tdec  = (const float*)d_in[11];
    const float* w1    = (const float*)d_in[12];
    const float* w2    = (const float*)d_in[13];
    const float* uu    = (const float*)d_in[14];
    const float* Wr    = (const float*)d_in[15];
    const float* Wk    = (const float*)d_in[16];
    const float* Wv    = (const float*)d_in[17];
    const float* Wo    = (const float*)d_in[18];
    const float* lng   = (const float*)d_in[19];
    const float* lnb   = (const float*)d_in[20];

    prep_coef_kernel<<<1, 512>>>(c1, c3, c5, alpha);
    prep_w_kernel<<<(4*CC*CC/8)/256, 256>>>(Wr, Wk, Wv, Wo);
    conv_shift2_kernel<<<dim3(HS, BB, 2), 256>>>(x);
    fused_dp2_kernel<<<dim3(TT/TP, BB, 2), 256>>>(x, maa_w, maa_r, maa_k, maa_v, tdec, w1, w2);

    // all 6 r/k/v GEMMs in ONE launch (z = dir*3 + variant)
    gemm_bf16_kernel<<<dim3(CC/256, MM/128, 6), 256>>>(nullptr, 1);

    wkv_pass1_kernel<<<(NUNIT*NCHUNK*16)/128, 128>>>();
    wkv_pass2_kernel<<<(NUNIT*16)/128, 128>>>();
    wkv_pass3_kernel<<<(NUNIT*NCHUNK*16)/128, 128>>>(uu);

    combine_ln_kernel<<<dim3(TT, BB), 128>>>(lng, lnb);
    gemm_bf16_kernel<<<dim3(CC/256, MM/128, 1), 256>>>((float*)d_out, 0);
}

// round 14
// speedup vs baseline: 1.2028x; 1.2028x over previous
#include <cuda_runtime.h>
#include <cuda_bf16.h>
#include <cstdint>

#define BB 8
#define TT 2304
#define CC 512
#define HS 48
#define HH 64
#define NN 8
#define MM (BB*TT)
#define BTC (MM*CC)
#define NCHUNK 24
#define CLEN 96          // TT / NCHUNK
#define NUNIT 1024       // 2 * BB * HH
#define TP 32            // positions per fused_dp2 block

// ---------------- scratch (device globals) ----------------
__device__ float g_xx[2*BTC];
__device__ float g_r [2*BTC];    // head-major: [dir][b][h][t][n]
__device__ float g_k [2*BTC];
__device__ float g_v [2*BTC];
__device__ float g_d [2*BTC];
__device__ float g_y [2*BTC];
__device__ float g_coef[25*CC];
// bf16 hi/lo planes: A variants 0..5 = dir*3 + {r,k,v}; 6 = layernormed
__device__ uint16_t g_Ahi[7*(size_t)BTC];
__device__ uint16_t g_Alo[7*(size_t)BTC];
__device__ uint16_t g_Whi[4*CC*CC];
__device__ uint16_t g_Wlo[4*CC*CC];
// chunked scan scratch
__device__ float g_M [NUNIT*NCHUNK*64];
__device__ float g_P [NUNIT*NCHUNK*8];
__device__ float g_S0[NUNIT*NCHUNK*64];

__device__ __forceinline__ float4 ld4(const float* p) { return *(const float4*)p; }

// head-major plane index: element (dir,b,h,t,0)
__device__ __forceinline__ size_t hplane(int dir, int b, int h, int t) {
    return ((((size_t)dir*BB + b)*HH + h)*(size_t)TT + t)*NN;
}

__device__ __forceinline__ void bfsplit4(float4 v, uint2& hi, uint2& lo) {
    __nv_bfloat16 hx = __float2bfloat16(v.x);
    __nv_bfloat16 hy = __float2bfloat16(v.y);
    __nv_bfloat16 hz = __float2bfloat16(v.z);
    __nv_bfloat16 hw = __float2bfloat16(v.w);
    float rx = v.x - __bfloat162float(hx);
    float ry = v.y - __bfloat162float(hy);
    float rz = v.z - __bfloat162float(hz);
    float rw = v.w - __bfloat162float(hw);
    __nv_bfloat16 lx = __float2bfloat16(rx);
    __nv_bfloat16 ly = __float2bfloat16(ry);
    __nv_bfloat16 lz = __float2bfloat16(rz);
    __nv_bfloat16 lw = __float2bfloat16(rw);
    hi.x = ((uint32_t)__bfloat16_as_ushort(hy) << 16) | __bfloat16_as_ushort(hx);
    hi.y = ((uint32_t)__bfloat16_as_ushort(hw) << 16) | __bfloat16_as_ushort(hz);
    lo.x = ((uint32_t)__bfloat16_as_ushort(ly) << 16) | __bfloat16_as_ushort(lx);
    lo.y = ((uint32_t)__bfloat16_as_ushort(lw) << 16) | __bfloat16_as_ushort(lz);
}

// ---------------- merged stencil coefficients ----------------
__global__ void prep_coef_kernel(const float* __restrict__ c1,
                                 const float* __restrict__ c3,
                                 const float* __restrict__ c5,
                                 const float* __restrict__ alpha)
{
    const int c = threadIdx.x;   // 512
    const float a0 = alpha[0], a1 = alpha[1], a2 = alpha[2], a3 = alpha[3];
    #pragma unroll
    for (int i = 0; i < 5; ++i) {
        #pragma unroll
        for (int j = 0; j < 5; ++j) {
            float w = a3 * c5[c*25 + i*5 + j];
            if (i >= 1 && i <= 3 && j >= 1 && j <= 3)
                w += a2 * c3[c*9 + (i-1)*3 + (j-1)];
            if (i == 2 && j == 2)
                w += a1 * c1[c] + a0 - 1.0f;    // -1: xx = sh - x
            g_coef[(i*5+j)*CC + c] = w;
        }
    }
}

// ---------------- conv shift v2: register-window stencil ----------------
__global__ __launch_bounds__(256)
void conv_shift2_kernel(const float* __restrict__ x)
{
    const int u   = blockIdx.x;
    const int b   = blockIdx.y;
    const int dir = blockIdx.z;
    const int c0  = (threadIdx.x & 127) * 4;
    const int qh  = threadIdx.x >> 7;
    const float* xb = x + (size_t)b*TT*CC;
    float* xxb = g_xx + (size_t)dir*BTC + (size_t)b*TT*CC;

    for (int ch = 0; ch < 3; ++ch) {
        const int q0 = qh*24 + ch*8;
        float4 acc[8];
        #pragma unroll
        for (int qi = 0; qi < 8; ++qi) acc[qi] = make_float4(0.f, 0.f, 0.f, 0.f);

        #pragma unroll
        for (int i = 0; i < 5; ++i) {
            const int uu = u + i - 2;
            if (uu < 0 || uu >= HS) continue;
            float4 xwin[12];
            #pragma unroll
            for (int t = 0; t < 12; ++t) {
                const int qq = q0 - 2 + t;
                if (qq >= 0 && qq < HS) {
                    const int idx = dir ? (qq*HS + uu) : (uu*HS + qq);
                    xwin[t] = ld4(xb + (size_t)idx*CC + c0);
                } else {
                    xwin[t] = make_float4(0.f, 0.f, 0.f, 0.f);
                }
            }
            #pragma unroll
            for (int j = 0; j < 5; ++j) {
                const float4 cf = ld4(g_coef + (i*5+j)*CC + c0);
                #pragma unroll
                for (int qi = 0; qi < 8; ++qi) {
                    const float4 xv = xwin[qi + j];
                    acc[qi].x = fmaf(cf.x, xv.x, acc[qi].x);
                    acc[qi].y = fmaf(cf.y, xv.y, acc[qi].y);
                    acc[qi].z = fmaf(cf.z, xv.z, acc[qi].z);
                    acc[qi].w = fmaf(cf.w, xv.w, acc[qi].w);
                }
            }
        }
        #pragma unroll
        for (int qi = 0; qi < 8; ++qi)
            *(float4*)(xxb + (size_t)(u*HS + q0 + qi)*CC + c0) = acc[qi];
    }
}

// ---------------- fused decay + bf16 plane prep, v2.1 (d stored head-major) ----------------
__global__ __launch_bounds__(256)
void fused_dp2_kernel(const float* __restrict__ x,
                      const float* __restrict__ maa_w,
                      const float* __restrict__ maar,
                      const float* __restrict__ maak,
                      const float* __restrict__ maav,
                      const float* __restrict__ tdec,
                      const float* __restrict__ w1,   // [C][16]
                      const float* __restrict__ w2)   // [16][C]
{
    __shared__ float w1s[16*CC];     // w1 transposed [j][c]; reused for w2 [j][c]
    __shared__ float maas[4*CC];     // r,k,v,w
    __shared__ float Hs[TP][16];

    const int tid = threadIdx.x;
    const int t0  = blockIdx.x * TP;
    const int b   = blockIdx.y;
    const int dir = blockIdx.z;

    for (int idx = tid; idx < 16*CC; idx += 256) {
        const int c = idx >> 4, j = idx & 15;
        w1s[j*CC + c] = w1[c*16 + j];
    }
    if (tid < 128) {
        ((float4*)maas)[tid]           = ld4(maar + tid*4);
        ((float4*)(maas + CC))[tid]    = ld4(maak + tid*4);
        ((float4*)(maas + 2*CC))[tid]  = ld4(maav + tid*4);
        ((float4*)(maas + 3*CC))[tid]  = ld4(maa_w + tid*4);
    }
    __syncthreads();

    const int p = tid >> 3;          // 0..31 position
    const int s = tid & 7;           // 0..7 channel slice
    const int t = t0 + p;
    const int m = b*TT + t;
    const int row = dir ? (b*TT + (t % HS)*HS + (t / HS)) : m;
    const size_t xxbase = (size_t)dir*BTC + (size_t)m*CC;
    const size_t u2base = (size_t)m*128;

    float h[16];
    #pragma unroll
    for (int j = 0; j < 16; ++j) h[j] = 0.0f;

    #pragma unroll 4
    for (int i = 0; i < 16; ++i) {
        const int c = (i*8 + s)*4;
        const float4 xv = ld4(x + (size_t)row*CC + c);
        const float4 xx = ld4(g_xx + xxbase + c);

        #pragma unroll
        for (int v = 0; v < 3; ++v) {
            const float4 mv = ld4(maas + v*CC + c);
            float4 a;
            a.x = fmaf(xx.x, mv.x, xv.x); a.y = fmaf(xx.y, mv.y, xv.y);
            a.z = fmaf(xx.z, mv.z, xv.z); a.w = fmaf(xx.w, mv.w, xv.w);
            uint2 hi, lo; bfsplit4(a, hi, lo);
            const size_t vb = (size_t)(dir*3 + v) * BTC;
            ((uint2*)(g_Ahi + vb))[u2base + c/4] = hi;
            ((uint2*)(g_Alo + vb))[u2base + c/4] = lo;
        }

        const float4 mw = ld4(maas + 3*CC + c);
        const float v0 = fmaf(xx.x, mw.x, xv.x);
        const float v1 = fmaf(xx.y, mw.y, xv.y);
        const float v2 = fmaf(xx.z, mw.z, xv.z);
        const float v3 = fmaf(xx.w, mw.w, xv.w);
        #pragma unroll
        for (int j = 0; j < 16; ++j) {
            const float4 w4 = *(const float4*)(w1s + j*CC + c);
            h[j] = fmaf(v0, w4.x, h[j]);
            h[j] = fmaf(v1, w4.y, h[j]);
            h[j] = fmaf(v2, w4.z, h[j]);
            h[j] = fmaf(v3, w4.w, h[j]);
        }
    }

    #pragma unroll
    for (int j = 0; j < 16; ++j) {
        h[j] += __shfl_xor_sync(0xffffffffu, h[j], 1);
        h[j] += __shfl_xor_sync(0xffffffffu, h[j], 2);
        h[j] += __shfl_xor_sync(0xffffffffu, h[j], 4);
    }
    if (s == 0) {
        #pragma unroll
        for (int j = 0; j < 16; ++j) Hs[p][j] = tanhf(h[j]);
    }
    __syncthreads();

    for (int idx4 = tid; idx4 < 16*CC/4; idx4 += 256)
        ((float4*)w1s)[idx4] = ((const float4*)w2)[idx4];
    __syncthreads();

    const int c0 = tid*2;
    float w2a[16], w2b[16];
    #pragma unroll
    for (int j = 0; j < 16; ++j) { w2a[j] = w1s[j*CC + c0]; w2b[j] = w1s[j*CC + c0 + 1]; }
    const float td0 = tdec[c0], td1 = tdec[c0+1];
    // head-major d: channel c0 -> (h = c0>>3, n0 = c0&7), stride NN per position
    float* dbase = g_d + hplane(dir, b, c0 >> 3, t0) + (c0 & 7);
    #pragma unroll 4
    for (int pp = 0; pp < TP; ++pp) {
        float a0 = td0, a1 = td1;
        #pragma unroll
        for (int j = 0; j < 16; ++j) {
            const float hj = Hs[pp][j];
            a0 = fmaf(hj, w2a[j], a0);
            a1 = fmaf(hj, w2b[j], a1);
        }
        *(float2*)(dbase + (size_t)pp*NN) = make_float2(expf(-expf(a0)), expf(-expf(a1)));
    }
}

// ---------------- prep: W -> bf16 hi/lo planes (8 ch/thread) ----------------
__global__ void prep_w_kernel(const float* __restrict__ Wr, const float* __restrict__ Wk,
                              const float* __restrict__ Wv, const float* __restrict__ Wo)
{
    const int idx = blockIdx.x*256 + threadIdx.x;       // over 4*CC*CC/8
    const int w = idx >> 15;                             // CC*CC/8 = 32768
    const int r = idx & 32767;
    const float* W = (w==0) ? Wr : (w==1) ? Wk : (w==2) ? Wv : Wo;
    const float4 va = ld4(W + (size_t)r*8);
    const float4 vb = ld4(W + (size_t)r*8 + 4);
    uint2 ha, la, hb, lb;
    bfsplit4(va, ha, la);
    bfsplit4(vb, hb, lb);
    ((uint4*)(g_Whi + (size_t)w*CC*CC))[r] = make_uint4(ha.x, ha.y, hb.x, hb.y);
    ((uint4*)(g_Wlo + (size_t)w*CC*CC))[r] = make_uint4(la.x, la.y, lb.x, lb.y);
}

// ---------------- bf16-split tensor-core GEMM, 128x256 tile, 2-stage static (round-10 cfg) ----------------
// per stage: Ahi 4KB | Alo 4KB | Bhi 8KB | Blo 8KB = 24KB; 2 stages = 48KB
#define ST3_B 24576
#define O_ALO 4096
#define O_BHI 8192
#define O_BLO 16384

__device__ __forceinline__ void cp16(uint32_t dst, const void* src) {
    asm volatile("cp.async.cg.shared.global [%0], [%1], 16;\n" :: "r"(dst), "l"(src));
}
__device__ __forceinline__ void ldsm4(uint32_t* r, uint32_t a) {
    asm volatile("ldmatrix.sync.aligned.m8n8.x4.shared.b16 {%0,%1,%2,%3}, [%4];"
        : "=r"(r[0]), "=r"(r[1]), "=r"(r[2]), "=r"(r[3]) : "r"(a));
}

__global__ __launch_bounds__(256)
void gemm_bf16_kernel(float* __restrict__ Out_ext, int a_sel, int w_sel, int out_sel, int dir)
{
    __shared__ uint32_t sm[2*ST3_B/4];   // 48KB

    const int tid = threadIdx.x;
    const int bn = blockIdx.x * 256;
    const int bm = blockIdx.y * 128;

    const uint16_t* Ah = g_Ahi + (size_t)a_sel*BTC;
    const uint16_t* Al = g_Alo + (size_t)a_sel*BTC;
    const uint16_t* Bh = g_Whi + (size_t)w_sel*CC*CC;
    const uint16_t* Bl = g_Wlo + (size_t)w_sel*CC*CC;
    float* Out;
    switch (out_sel) {
        case 0: Out = g_r; break;     // head-major, dir folded via hplane
        case 1: Out = g_k; break;
        case 2: Out = g_v; break;
        default: Out = Out_ext; break;
    }

    // ---- staging geometry ----
    const int rowA  = tid >> 1;                 // 0..127
    const int halfA = tid & 1;
    const int hswA  = halfA ^ ((rowA >> 2) & 1);
    const uint16_t* pa_h = Ah + (size_t)(bm + rowA)*CC + halfA*8;
    const uint16_t* pa_l = Al + (size_t)(bm + rowA)*CC + halfA*8;
    const uint32_t smbase = (uint32_t)__cvta_generic_to_shared(&sm[0]);
    const uint32_t doffA = (uint32_t)(rowA*32 + hswA*16);
    // B: 256 rows -> 2 chunks/thread/plane
    const int rowB2 = rowA + 128;
    const int hswB2 = halfA ^ ((rowB2 >> 2) & 1);
    const uint16_t* pb_h0 = Bh + (size_t)(bn + rowA)*CC + halfA*8;
    const uint16_t* pb_l0 = Bl + (size_t)(bn + rowA)*CC + halfA*8;
    const uint16_t* pb_h1 = Bh + (size_t)(bn + rowB2)*CC + halfA*8;
    const uint16_t* pb_l1 = Bl + (size_t)(bn + rowB2)*CC + halfA*8;
    const uint32_t doffB0 = doffA;
    const uint32_t doffB1 = (uint32_t)(rowB2*32 + hswB2*16);

    const int lane = tid & 31;
    const int grp  = lane >> 2;
    const int qid  = lane & 3;
    const int wid  = tid >> 5;
    const int wm   = wid >> 2;      // 0..1 -> 64 M rows
    const int wn   = wid & 3;       // 0..3 -> 64 N cols

    const int selA = lane >> 3;
    const int rA   = wm*64 + ((selA & 1) << 3) + (lane & 7);
    const int hA   = (selA >> 1) ^ ((rA >> 2) & 1);
    const uint32_t offA = (uint32_t)(rA*32 + hA*16);
    const int rB0  = wn*64 + ((lane >> 4) << 3) + (lane & 7);
    const int hB4  = ((lane >> 3) & 1) ^ ((rB0 >> 2) & 1);
    const uint32_t offB4 = (uint32_t)(rB0*32 + hB4*16);

    float c[4][8][4];
    #pragma unroll
    for (int mt = 0; mt < 4; ++mt)
        #pragma unroll
        for (int nt = 0; nt < 8; ++nt)
            #pragma unroll
            for (int e = 0; e < 4; ++e) c[mt][nt][e] = 0.0f;

    // prologue: prefetch ktiles 0,1 into stages 0,1
    #pragma unroll
    for (int kt = 0; kt < 2; ++kt) {
        const uint32_t d = smbase + kt*ST3_B;
        const int off = kt*16;
        cp16(d + doffA, pa_h + off);
        cp16(d + O_ALO + doffA, pa_l + off);
        cp16(d + O_BHI + doffB0, pb_h0 + off);
        cp16(d + O_BHI + doffB1, pb_h1 + off);
        cp16(d + O_BLO + doffB0, pb_l0 + off);
        cp16(d + O_BLO + doffB1, pb_l1 + off);
        asm volatile("cp.async.commit_group;\n");
    }

    for (int kt = 0; kt < 32; ++kt) {
        const int p = kt & 1;
        asm volatile("cp.async.wait_group 1;\n");
        __syncthreads();

        const uint32_t sb = smbase + p*ST3_B;
        uint32_t ah[4][4], al[4][4], bh[8][2], bl[8][2];
        #pragma unroll
        for (int mt = 0; mt < 4; ++mt) ldsm4(ah[mt], sb + mt*512 + offA);
        #pragma unroll
        for (int mt = 0; mt < 4; ++mt) ldsm4(al[mt], sb + O_ALO + mt*512 + offA);
        #pragma unroll
        for (int np = 0; np < 4; ++np) {
            uint32_t btmp[4];
            ldsm4(btmp, sb + O_BHI + np*512 + offB4);
            bh[2*np][0] = btmp[0]; bh[2*np][1] = btmp[1];
            bh[2*np+1][0] = btmp[2]; bh[2*np+1][1] = btmp[3];
            ldsm4(btmp, sb + O_BLO + np*512 + offB4);
            bl[2*np][0] = btmp[0]; bl[2*np][1] = btmp[1];
            bl[2*np+1][0] = btmp[2]; bl[2*np+1][1] = btmp[3];
        }

        #pragma unroll
        for (int mt = 0; mt < 4; ++mt) {
            #pragma unroll
            for (int nt = 0; nt < 8; ++nt) {
                asm volatile(
                    "mma.sync.aligned.m16n8k16.row.col.f32.bf16.bf16.f32 "
                    "{%0,%1,%2,%3}, {%4,%5,%6,%7}, {%8,%9}, {%0,%1,%2,%3};"
                    : "+f"(c[mt][nt][0]), "+f"(c[mt][nt][1]),
                      "+f"(c[mt][nt][2]), "+f"(c[mt][nt][3])
                    : "r"(ah[mt][0]), "r"(ah[mt][1]), "r"(ah[mt][2]), "r"(ah[mt][3]),
                      "r"(bh[nt][0]), "r"(bh[nt][1]));
                asm volatile(
                    "mma.sync.aligned.m16n8k16.row.col.f32.bf16.bf16.f32 "
                    "{%0,%1,%2,%3}, {%4,%5,%6,%7}, {%8,%9}, {%0,%1,%2,%3};"
                    : "+f"(c[mt][nt][0]), "+f"(c[mt][nt][1]),
                      "+f"(c[mt][nt][2]), "+f"(c[mt][nt][3])
                    : "r"(al[mt][0]), "r"(al[mt][1]), "r"(al[mt][2]), "r"(al[mt][3]),
                      "r"(bh[nt][0]), "r"(bh[nt][1]));
                asm volatile(
                    "mma.sync.aligned.m16n8k16.row.col.f32.bf16.bf16.f32 "
                    "{%0,%1,%2,%3}, {%4,%5,%6,%7}, {%8,%9}, {%0,%1,%2,%3};"
                    : "+f"(c[mt][nt][0]), "+f"(c[mt][nt][1]),
                      "+f"(c[mt][nt][2]), "+f"(c[mt][nt][3])
                    : "r"(ah[mt][0]), "r"(ah[mt][1]), "r"(ah[mt][2]), "r"(ah[mt][3]),
                      "r"(bl[nt][0]), "r"(bl[nt][1]));
            }
        }

        __syncthreads();
        if (kt + 2 < 32) {
            const uint32_t d = smbase + p*ST3_B;
            const int off = (kt+2)*16;
            cp16(d + doffA, pa_h + off);
            cp16(d + O_ALO + doffA, pa_l + off);
            cp16(d + O_BHI + doffB0, pb_h0 + off);
            cp16(d + O_BHI + doffB1, pb_h1 + off);
            cp16(d + O_BLO + doffB0, pb_l0 + off);
            cp16(d + O_BLO + doffB1, pb_l1 + off);
        }
        asm volatile("cp.async.commit_group;\n");
    }

    // epilogue
    if (out_sel <= 2) {
        // head-major store: tile rows all in one batch b (TT = 18*128)
        const int b = bm / TT;
        #pragma unroll
        for (int mt = 0; mt < 4; ++mt) {
            const int rrow = bm + wm*64 + mt*16 + grp;
            const int t = rrow - b*TT;
            #pragma unroll
            for (int nt = 0; nt < 8; ++nt) {
                const int col = bn + wn*64 + nt*8 + qid*2;
                const int hh = col >> 3, n = col & 7;
                float* po = Out + hplane(dir, b, hh, t) + n;
                *(float2*)po            = make_float2(c[mt][nt][0], c[mt][nt][1]);
                *(float2*)(po + 8*NN)   = make_float2(c[mt][nt][2], c[mt][nt][3]);  // t+8
            }
        }
    } else {
        #pragma unroll
        for (int mt = 0; mt < 4; ++mt) {
            const int rrow = bm + wm*64 + mt*16 + grp;
            #pragma unroll
            for (int nt = 0; nt < 8; ++nt) {
                const int col = bn + wn*64 + nt*8 + qid*2;
                *(float2*)(Out + (size_t)rrow*CC + col)     = make_float2(c[mt][nt][0], c[mt][nt][1]);
                *(float2*)(Out + (size_t)(rrow+8)*CC + col) = make_float2(c[mt][nt][2], c[mt][nt][3]);
            }
        }
    }
}

// ---------------- WKV6 chunked scan (head-major operands, stride NN per step) ----------------
__global__ void wkv_pass1_kernel()
{
    const int gt = blockIdx.x*128 + threadIdx.x;
    const int s = gt & 15;
    const int j = s & 7, p = s >> 3;
    const int i0 = p*4;
    const int ucid = gt >> 4;
    const int cch = ucid % NCHUNK;
    const int unit = ucid / NCHUNK;
    const int h = unit & 63, b = (unit >> 6) & 7, dir = unit >> 9;

    const size_t base = hplane(dir, b, h, cch*CLEN);
    const float* kk = g_k + base;
    const float* vv = g_v + base;
    const float* dd = g_d + base;

    float S0=0.f,S1=0.f,S2=0.f,S3=0.f, P0=1.f,P1=1.f,P2=1.f,P3=1.f;
    int off = 0;
    #pragma unroll 4
    for (int t = 0; t < CLEN; ++t, off += NN) {
        const float4 k4 = ld4(kk + off + i0);
        const float4 d4 = ld4(dd + off + i0);
        const float v = vv[off + j];
        S0 = fmaf(d4.x, S0, k4.x*v); P0 *= d4.x;
        S1 = fmaf(d4.y, S1, k4.y*v); P1 *= d4.y;
        S2 = fmaf(d4.z, S2, k4.z*v); P2 *= d4.z;
        S3 = fmaf(d4.w, S3, k4.w*v); P3 *= d4.w;
    }
    float* Mp = g_M + (size_t)ucid*64;
    Mp[(i0+0)*8 + j] = S0;
    Mp[(i0+1)*8 + j] = S1;
    Mp[(i0+2)*8 + j] = S2;
    Mp[(i0+3)*8 + j] = S3;
    if (j == 0) {
        float* Pp = g_P + (size_t)ucid*8;
        Pp[i0+0] = P0; Pp[i0+1] = P1; Pp[i0+2] = P2; Pp[i0+3] = P3;
    }
}

__global__ void wkv_pass2_kernel()
{
    const int gt = blockIdx.x*128 + threadIdx.x;   // 16384 threads
    const int s = gt & 15;
    const int j = s & 7, p = s >> 3;
    const int i0 = p*4;
    const int unit = gt >> 4;

    float S0=0.f,S1=0.f,S2=0.f,S3=0.f;
    for (int cch = 0; cch < NCHUNK; ++cch) {
        const size_t uc = (size_t)unit*NCHUNK + cch;
        float* Sp = g_S0 + uc*64;
        Sp[(i0+0)*8 + j] = S0;
        Sp[(i0+1)*8 + j] = S1;
        Sp[(i0+2)*8 + j] = S2;
        Sp[(i0+3)*8 + j] = S3;
        const float* Pp = g_P + uc*8;
        const float* Mp = g_M + uc*64;
        S0 = fmaf(Pp[i0+0], S0, Mp[(i0+0)*8 + j]);
        S1 = fmaf(Pp[i0+1], S1, Mp[(i0+1)*8 + j]);
        S2 = fmaf(Pp[i0+2], S2, Mp[(i0+2)*8 + j]);
        S3 = fmaf(Pp[i0+3], S3, Mp[(i0+3)*8 + j]);
    }
}

__global__ void wkv_pass3_kernel(const float* __restrict__ u)
{
    const int gt = blockIdx.x*128 + threadIdx.x;
    const int s = gt & 15;
    const int j = s & 7, p = s >> 3;
    const int i0 = p*4;
    const int ucid = gt >> 4;
    const int cch = ucid % NCHUNK;
    const int unit = ucid / NCHUNK;
    const int h = unit & 63, b = (unit >> 6) & 7, dir = unit >> 9;

    const float4 uu = ld4(u + h*NN + i0);
    const size_t base = hplane(dir, b, h, cch*CLEN);
    const float* rr = g_r + base;
    const float* kk = g_k + base;
    const float* vv = g_v + base;
    const float* dd = g_d + base;
    float* yy = g_y + base;

    const float* Sp = g_S0 + (size_t)ucid*64;
    float S0 = Sp[(i0+0)*8 + j];
    float S1 = Sp[(i0+1)*8 + j];
    float S2 = Sp[(i0+2)*8 + j];
    float S3 = Sp[(i0+3)*8 + j];

    int off = 0;
    #pragma unroll 2
    for (int t = 0; t < CLEN; ++t, off += NN) {
        const float4 r4 = ld4(rr + off + i0);
        const float4 k4 = ld4(kk + off + i0);
        const float4 d4 = ld4(dd + off + i0);
        const float v = vv[off + j];
        float y = 0.f, kv, tt;
        kv = k4.x*v; tt = fmaf(uu.x, kv, S0); y = fmaf(r4.x, tt, y); S0 = fmaf(d4.x, S0, kv);
        kv = k4.y*v; tt = fmaf(uu.y, kv, S1); y = fmaf(r4.y, tt, y); S1 = fmaf(d4.y, S1, kv);
        kv = k4.z*v; tt = fmaf(uu.z, kv, S2); y = fmaf(r4.z, tt, y); S2 = fmaf(d4.z, S2, kv);
        kv = k4.w*v; tt = fmaf(uu.w, kv, S3); y = fmaf(r4.w, tt, y); S3 = fmaf(d4.w, S3, kv);
        y += __shfl_xor_sync(0xffffffffu, y, 8);
        if (p == 0) yy[off + j] = y;
    }
}

// ---------------- combine directions + layernorm -> bf16 hi/lo planes (slot 6) ----------------
__global__ void combine_ln_kernel(const float* __restrict__ lng,
                                  const float* __restrict__ lnb)
{
    const int t = blockIdx.x, b = blockIdx.y;
    const int tid = threadIdx.x;   // 128
    const int c0 = tid*4;
    const int hh = c0 >> 3, n0 = c0 & 7;   // n0 in {0,4}: float4 stays within head
    const int y = t / HS, xq = t % HS;
    const int tcol = xq*HS + y;
    const int m = b*TT + t;

    const float4 va = ld4(g_y + hplane(0, b, hh, t)    + n0);
    const float4 vb = ld4(g_y + hplane(1, b, hh, tcol) + n0);
    float4 o;
    o.x = 0.5f*(va.x + vb.x); o.y = 0.5f*(va.y + vb.y);
    o.z = 0.5f*(va.z + vb.z); o.w = 0.5f*(va.w + vb.w);
    float s  = o.x + o.y + o.z + o.w;
    float sq = o.x*o.x + o.y*o.y + o.z*o.z + o.w*o.w;
    #pragma unroll
    for (int off = 16; off > 0; off >>= 1) {
        s  += __shfl_xor_sync(0xffffffffu, s,  off);
        sq += __shfl_xor_sync(0xffffffffu, sq, off);
    }
    __shared__ float ss[4], sqs[4];
    if ((tid & 31) == 0) { ss[tid >> 5] = s; sqs[tid >> 5] = sq; }
    __syncthreads();
    s  = ss[0] + ss[1] + ss[2] + ss[3];
    sq = sqs[0] + sqs[1] + sqs[2] + sqs[3];
    const float mu = s * (1.0f/CC);
    const float var = sq * (1.0f/CC) - mu*mu;
    const float rstd = rsqrtf(var + 1e-5f);

    const float4 g4 = ld4(lng + c0);
    const float4 b4 = ld4(lnb + c0);
    float4 res;
    res.x = (o.x - mu)*rstd*g4.x + b4.x;
    res.y = (o.y - mu)*rstd*g4.y + b4.y;
    res.z = (o.z - mu)*rstd*g4.z + b4.z;
    res.w = (o.w - mu)*rstd*g4.w + b4.w;
    uint2 hi, lo;
    bfsplit4(res, hi, lo);
    const size_t u2idx = (size_t)m*128 + tid;
    ((uint2*)(g_Ahi + (size_t)6*BTC))[u2idx] = hi;
    ((uint2*)(g_Alo + (size_t)6*BTC))[u2idx] = lo;
}

// ---------------- launch ----------------
extern "C" void kernel_launch(void* const* d_in, const int* in_sizes, int n_in,
                              void* d_out, int out_size)
{
    (void)in_sizes; (void)n_in; (void)out_size;
    const float* x     = (const float*)d_in[0];
    const float* c1    = (const float*)d_in[3];
    const float* c3    = (const float*)d_in[4];
    const float* c5    = (const float*)d_in[5];
    const float* alpha = (const float*)d_in[6];
    const float* maa_w = (const float*)d_in[7];
    const float* maa_k = (const float*)d_in[8];
    const float* maa_v = (const float*)d_in[9];
    const float* maa_r = (const float*)d_in[10];
    const float* tdec  = (const float*)d_in[11];
    const float* w1    = (const float*)d_in[12];
    const float* w2    = (const float*)d_in[13];
    const float* uu    = (const float*)d_in[14];
    const float* Wr    = (const float*)d_in[15];
    const float* Wk    = (const float*)d_in[16];
    const float* Wv    = (const float*)d_in[17];
    const float* Wo    = (const float*)d_in[18];
    const float* lng   = (const float*)d_in[19];
    const float* lnb   = (const float*)d_in[20];

    prep_coef_kernel<<<1, 512>>>(c1, c3, c5, alpha);
    prep_w_kernel<<<(4*CC*CC/8)/256, 256>>>(Wr, Wk, Wv, Wo);
    conv_shift2_kernel<<<dim3(HS, BB, 2), 256>>>(x);
    fused_dp2_kernel<<<dim3(TT/TP, BB, 2), 256>>>(x, maa_w, maa_r, maa_k, maa_v, tdec, w1, w2);

    const dim3 ggrid(CC/256, MM/128);   // (2, 144)
    for (int dir = 0; dir < 2; ++dir) {
        gemm_bf16_kernel<<<ggrid, 256>>>(nullptr, dir*3+0, 0, 0, dir);
        gemm_bf16_kernel<<<ggrid, 256>>>(nullptr, dir*3+1, 1, 1, dir);
        gemm_bf16_kernel<<<ggrid, 256>>>(nullptr, dir*3+2, 2, 2, dir);
    }

    wkv_pass1_kernel<<<(NUNIT*NCHUNK*16)/128, 128>>>();
    wkv_pass2_kernel<<<(NUNIT*16)/128, 128>>>();
    wkv_pass3_kernel<<<(NUNIT*NCHUNK*16)/128, 128>>>(uu);

    combine_ln_kernel<<<dim3(TT, BB), 128>>>(lng, lnb);
    gemm_bf16_kernel<<<ggrid, 256>>>((float*)d_out, 6, 3, 3, 0);
}

// round 16
// speedup vs baseline: 1.2236x; 1.0173x over previous
#include <cuda_runtime.h>
#include <cuda_bf16.h>
#include <cstdint>

#define BB 8
#define TT 2304
#define CC 512
#define HS 48
#define HH 64
#define NN 8
#define MM (BB*TT)
#define BTC (MM*CC)
#define NCHUNK 24
#define CLEN 96          // TT / NCHUNK
#define NUNIT 1024       // 2 * BB * HH
#define TP 32            // positions per fused_dp2 block

// ---------------- scratch (device globals) ----------------
__device__ float g_xx[2*BTC];
__device__ float g_r [2*BTC];    // head-major: [dir][b][h][t][n]
__device__ float g_k [2*BTC];
__device__ float g_v [2*BTC];
__device__ float g_d [2*BTC];
__device__ float g_y [2*BTC];
__device__ float g_coef[25*CC];
// bf16 hi/lo planes: A variants 0..5 = dir*3 + {r,k,v}; 6 = layernormed
__device__ uint16_t g_Ahi[7*(size_t)BTC];
__device__ uint16_t g_Alo[7*(size_t)BTC];
__device__ uint16_t g_Whi[4*CC*CC];
__device__ uint16_t g_Wlo[4*CC*CC];
// chunked scan scratch
__device__ float g_M [NUNIT*NCHUNK*64];
__device__ float g_P [NUNIT*NCHUNK*8];
__device__ float g_S0[NUNIT*NCHUNK*64];

__device__ __forceinline__ float4 ld4(const float* p) { return *(const float4*)p; }

// head-major plane index: element (dir,b,h,t,0)
__device__ __forceinline__ size_t hplane(int dir, int b, int h, int t) {
    return ((((size_t)dir*BB + b)*HH + h)*(size_t)TT + t)*NN;
}
// 32-bit variant (all scratch offsets < 2^31)
__device__ __forceinline__ uint32_t hplane32(int dir, int b, int h, int t) {
    return ((((uint32_t)dir*BB + (uint32_t)b)*HH + (uint32_t)h)*(uint32_t)TT + (uint32_t)t)*NN;
}

__device__ __forceinline__ void bfsplit4(float4 v, uint2& hi, uint2& lo) {
    __nv_bfloat16 hx = __float2bfloat16(v.x);
    __nv_bfloat16 hy = __float2bfloat16(v.y);
    __nv_bfloat16 hz = __float2bfloat16(v.z);
    __nv_bfloat16 hw = __float2bfloat16(v.w);
    float rx = v.x - __bfloat162float(hx);
    float ry = v.y - __bfloat162float(hy);
    float rz = v.z - __bfloat162float(hz);
    float rw = v.w - __bfloat162float(hw);
    __nv_bfloat16 lx = __float2bfloat16(rx);
    __nv_bfloat16 ly = __float2bfloat16(ry);
    __nv_bfloat16 lz = __float2bfloat16(rz);
    __nv_bfloat16 lw = __float2bfloat16(rw);
    hi.x = ((uint32_t)__bfloat16_as_ushort(hy) << 16) | __bfloat16_as_ushort(hx);
    hi.y = ((uint32_t)__bfloat16_as_ushort(hw) << 16) | __bfloat16_as_ushort(hz);
    lo.x = ((uint32_t)__bfloat16_as_ushort(ly) << 16) | __bfloat16_as_ushort(lx);
    lo.y = ((uint32_t)__bfloat16_as_ushort(lw) << 16) | __bfloat16_as_ushort(lz);
}

// ---------------- merged stencil coefficients ----------------
__global__ void prep_coef_kernel(const float* __restrict__ c1,
                                 const float* __restrict__ c3,
                                 const float* __restrict__ c5,
                                 const float* __restrict__ alpha)
{
    const int c = threadIdx.x;   // 512
    const float a0 = alpha[0], a1 = alpha[1], a2 = alpha[2], a3 = alpha[3];
    #pragma unroll
    for (int i = 0; i < 5; ++i) {
        #pragma unroll
        for (int j = 0; j < 5; ++j) {
            float w = a3 * c5[c*25 + i*5 + j];
            if (i >= 1 && i <= 3 && j >= 1 && j <= 3)
                w += a2 * c3[c*9 + (i-1)*3 + (j-1)];
            if (i == 2 && j == 2)
                w += a1 * c1[c] + a0 - 1.0f;    // -1: xx = sh - x
            g_coef[(i*5+j)*CC + c] = w;
        }
    }
}

// ---------------- conv shift v2: register-window stencil ----------------
__global__ __launch_bounds__(256)
void conv_shift2_kernel(const float* __restrict__ x)
{
    const int u   = blockIdx.x;
    const int b   = blockIdx.y;
    const int dir = blockIdx.z;
    const int c0  = (threadIdx.x & 127) * 4;
    const int qh  = threadIdx.x >> 7;
    const float* xb = x + (size_t)b*TT*CC;
    float* xxb = g_xx + (size_t)dir*BTC + (size_t)b*TT*CC;

    for (int ch = 0; ch < 3; ++ch) {
        const int q0 = qh*24 + ch*8;
        float4 acc[8];
        #pragma unroll
        for (int qi = 0; qi < 8; ++qi) acc[qi] = make_float4(0.f, 0.f, 0.f, 0.f);

        #pragma unroll
        for (int i = 0; i < 5; ++i) {
            const int uu = u + i - 2;
            if (uu < 0 || uu >= HS) continue;
            float4 xwin[12];
            #pragma unroll
            for (int t = 0; t < 12; ++t) {
                const int qq = q0 - 2 + t;
                if (qq >= 0 && qq < HS) {
                    const int idx = dir ? (qq*HS + uu) : (uu*HS + qq);
                    xwin[t] = ld4(xb + (size_t)idx*CC + c0);
                } else {
                    xwin[t] = make_float4(0.f, 0.f, 0.f, 0.f);
                }
            }
            #pragma unroll
            for (int j = 0; j < 5; ++j) {
                const float4 cf = ld4(g_coef + (i*5+j)*CC + c0);
                #pragma unroll
                for (int qi = 0; qi < 8; ++qi) {
                    const float4 xv = xwin[qi + j];
                    acc[qi].x = fmaf(cf.x, xv.x, acc[qi].x);
                    acc[qi].y = fmaf(cf.y, xv.y, acc[qi].y);
                    acc[qi].z = fmaf(cf.z, xv.z, acc[qi].z);
                    acc[qi].w = fmaf(cf.w, xv.w, acc[qi].w);
                }
            }
        }
        #pragma unroll
        for (int qi = 0; qi < 8; ++qi)
            *(float4*)(xxb + (size_t)(u*HS + q0 + qi)*CC + c0) = acc[qi];
    }
}

// ---------------- fused decay + bf16 plane prep (d head-major, 32-bit addressing) ----------------
__global__ __launch_bounds__(256)
void fused_dp2_kernel(const float* __restrict__ x,
                      const float* __restrict__ maa_w,
                      const float* __restrict__ maar,
                      const float* __restrict__ maak,
                      const float* __restrict__ maav,
                      const float* __restrict__ tdec,
                      const float* __restrict__ w1,   // [C][16]
                      const float* __restrict__ w2)   // [16][C]
{
    __shared__ float w1s[16*CC];     // w1 transposed [j][c]; reused for w2 [j][c]
    __shared__ float maas[4*CC];     // r,k,v,w
    __shared__ float Hs[TP][16];

    const int tid = threadIdx.x;
    const int t0  = blockIdx.x * TP;
    const int b   = blockIdx.y;
    const int dir = blockIdx.z;

    for (int idx = tid; idx < 16*CC; idx += 256) {
        const int c = idx >> 4, j = idx & 15;
        w1s[j*CC + c] = w1[c*16 + j];
    }
    if (tid < 128) {
        ((float4*)maas)[tid]           = ld4(maar + tid*4);
        ((float4*)(maas + CC))[tid]    = ld4(maak + tid*4);
        ((float4*)(maas + 2*CC))[tid]  = ld4(maav + tid*4);
        ((float4*)(maas + 3*CC))[tid]  = ld4(maa_w + tid*4);
    }
    __syncthreads();

    const int p = tid >> 3;          // 0..31 position
    const int s = tid & 7;           // 0..7 channel slice
    const int t = t0 + p;
    const int m = b*TT + t;
    const int row = dir ? (b*TT + (t % HS)*HS + (t / HS)) : m;
    const uint32_t xxbase = (uint32_t)dir*BTC + (uint32_t)m*CC;
    const uint32_t u2base = (uint32_t)m*128;

    float h[16];
    #pragma unroll
    for (int j = 0; j < 16; ++j) h[j] = 0.0f;

    #pragma unroll 4
    for (int i = 0; i < 16; ++i) {
        const int c = (i*8 + s)*4;
        const float4 xv = ld4(x + (size_t)row*CC + c);
        const float4 xx = ld4(g_xx + xxbase + c);

        #pragma unroll
        for (int v = 0; v < 3; ++v) {
            const float4 mv = ld4(maas + v*CC + c);
            float4 a;
            a.x = fmaf(xx.x, mv.x, xv.x); a.y = fmaf(xx.y, mv.y, xv.y);
            a.z = fmaf(xx.z, mv.z, xv.z); a.w = fmaf(xx.w, mv.w, xv.w);
            uint2 hi, lo; bfsplit4(a, hi, lo);
            const size_t vb = (size_t)(dir*3 + v) * BTC;
            ((uint2*)(g_Ahi + vb))[u2base + (uint32_t)(c >> 2)] = hi;
            ((uint2*)(g_Alo + vb))[u2base + (uint32_t)(c >> 2)] = lo;
        }

        const float4 mw = ld4(maas + 3*CC + c);
        const float v0 = fmaf(xx.x, mw.x, xv.x);
        const float v1 = fmaf(xx.y, mw.y, xv.y);
        const float v2 = fmaf(xx.z, mw.z, xv.z);
        const float v3 = fmaf(xx.w, mw.w, xv.w);
        #pragma unroll
        for (int j = 0; j < 16; ++j) {
            const float4 w4 = *(const float4*)(w1s + j*CC + c);
            h[j] = fmaf(v0, w4.x, h[j]);
            h[j] = fmaf(v1, w4.y, h[j]);
            h[j] = fmaf(v2, w4.z, h[j]);
            h[j] = fmaf(v3, w4.w, h[j]);
        }
    }

    #pragma unroll
    for (int j = 0; j < 16; ++j) {
        h[j] += __shfl_xor_sync(0xffffffffu, h[j], 1);
        h[j] += __shfl_xor_sync(0xffffffffu, h[j], 2);
        h[j] += __shfl_xor_sync(0xffffffffu, h[j], 4);
    }
    if (s == 0) {
        #pragma unroll
        for (int j = 0; j < 16; ++j) Hs[p][j] = tanhf(h[j]);
    }
    __syncthreads();

    for (int idx4 = tid; idx4 < 16*CC/4; idx4 += 256)
        ((float4*)w1s)[idx4] = ((const float4*)w2)[idx4];
    __syncthreads();

    const int c0 = tid*2;
    float w2a[16], w2b[16];
    #pragma unroll
    for (int j = 0; j < 16; ++j) { w2a[j] = w1s[j*CC + c0]; w2b[j] = w1s[j*CC + c0 + 1]; }
    const float td0 = tdec[c0], td1 = tdec[c0+1];
    // head-major d: channel c0 -> (h = c0>>3, n0 = c0&7); pure 32-bit addressing
    const uint32_t doff = hplane32(dir, b, c0 >> 3, t0) + (uint32_t)(c0 & 7);
    float* dbase = g_d + doff;
    #pragma unroll 4
    for (int pp = 0; pp < TP; ++pp) {
        float a0 = td0, a1 = td1;
        #pragma unroll
        for (int j = 0; j < 16; ++j) {
            const float hj = Hs[pp][j];
            a0 = fmaf(hj, w2a[j], a0);
            a1 = fmaf(hj, w2b[j], a1);
        }
        *(float2*)(dbase + (uint32_t)pp*NN) = make_float2(expf(-expf(a0)), expf(-expf(a1)));
    }
}

// ---------------- prep: W -> bf16 hi/lo planes (8 ch/thread) ----------------
__global__ void prep_w_kernel(const float* __restrict__ Wr, const float* __restrict__ Wk,
                              const float* __restrict__ Wv, const float* __restrict__ Wo)
{
    const int idx = blockIdx.x*256 + threadIdx.x;       // over 4*CC*CC/8
    const int w = idx >> 15;                             // CC*CC/8 = 32768
    const int r = idx & 32767;
    const float* W = (w==0) ? Wr : (w==1) ? Wk : (w==2) ? Wv : Wo;
    const float4 va = ld4(W + (size_t)r*8);
    const float4 vb = ld4(W + (size_t)r*8 + 4);
    uint2 ha, la, hb, lb;
    bfsplit4(va, ha, la);
    bfsplit4(vb, hb, lb);
    ((uint4*)(g_Whi + (size_t)w*CC*CC))[r] = make_uint4(ha.x, ha.y, hb.x, hb.y);
    ((uint4*)(g_Wlo + (size_t)w*CC*CC))[r] = make_uint4(la.x, la.y, lb.x, lb.y);
}

// ---------------- bf16-split tensor-core GEMM, 128x256 tile, 2-stage static (round-10 cfg) ----------------
// per stage: Ahi 4KB | Alo 4KB | Bhi 8KB | Blo 8KB = 24KB; 2 stages = 48KB
#define ST3_B 24576
#define O_ALO 4096
#define O_BHI 8192
#define O_BLO 16384

__device__ __forceinline__ void cp16(uint32_t dst, const void* src) {
    asm volatile("cp.async.cg.shared.global [%0], [%1], 16;\n" :: "r"(dst), "l"(src));
}
__device__ __forceinline__ void ldsm4(uint32_t* r, uint32_t a) {
    asm volatile("ldmatrix.sync.aligned.m8n8.x4.shared.b16 {%0,%1,%2,%3}, [%4];"
        : "=r"(r[0]), "=r"(r[1]), "=r"(r[2]), "=r"(r[3]) : "r"(a));
}

__global__ __launch_bounds__(256)
void gemm_bf16_kernel(float* __restrict__ Out_ext, int a_sel, int w_sel, int out_sel, int dir)
{
    __shared__ uint32_t sm[2*ST3_B/4];   // 48KB

    const int tid = threadIdx.x;
    const int bn = blockIdx.x * 256;
    const int bm = blockIdx.y * 128;

    const uint16_t* Ah = g_Ahi + (size_t)a_sel*BTC;
    const uint16_t* Al = g_Alo + (size_t)a_sel*BTC;
    const uint16_t* Bh = g_Whi + (size_t)w_sel*CC*CC;
    const uint16_t* Bl = g_Wlo + (size_t)w_sel*CC*CC;
    float* Out;
    switch (out_sel) {
        case 0: Out = g_r; break;     // head-major, dir folded via hplane
        case 1: Out = g_k; break;
        case 2: Out = g_v; break;
        default: Out = Out_ext; break;
    }

    // ---- staging geometry ----
    const int rowA  = tid >> 1;                 // 0..127
    const int halfA = tid & 1;
    const int hswA  = halfA ^ ((rowA >> 2) & 1);
    const uint16_t* pa_h = Ah + (size_t)(bm + rowA)*CC + halfA*8;
    const uint16_t* pa_l = Al + (size_t)(bm + rowA)*CC + halfA*8;
    const uint32_t smbase = (uint32_t)__cvta_generic_to_shared(&sm[0]);
    const uint32_t doffA = (uint32_t)(rowA*32 + hswA*16);
    // B: 256 rows -> 2 chunks/thread/plane
    const int rowB2 = rowA + 128;
    const int hswB2 = halfA ^ ((rowB2 >> 2) & 1);
    const uint16_t* pb_h0 = Bh + (size_t)(bn + rowA)*CC + halfA*8;
    const uint16_t* pb_l0 = Bl + (size_t)(bn + rowA)*CC + halfA*8;
    const uint16_t* pb_h1 = Bh + (size_t)(bn + rowB2)*CC + halfA*8;
    const uint16_t* pb_l1 = Bl + (size_t)(bn + rowB2)*CC + halfA*8;
    const uint32_t doffB0 = doffA;
    const uint32_t doffB1 = (uint32_t)(rowB2*32 + hswB2*16);

    const int lane = tid & 31;
    const int grp  = lane >> 2;
    const int qid  = lane & 3;
    const int wid  = tid >> 5;
    const int wm   = wid >> 2;      // 0..1 -> 64 M rows
    const int wn   = wid & 3;       // 0..3 -> 64 N cols

    const int selA = lane >> 3;
    const int rA   = wm*64 + ((selA & 1) << 3) + (lane & 7);
    const int hA   = (selA >> 1) ^ ((rA >> 2) & 1);
    const uint32_t offA = (uint32_t)(rA*32 + hA*16);
    const int rB0  = wn*64 + ((lane >> 4) << 3) + (lane & 7);
    const int hB4  = ((lane >> 3) & 1) ^ ((rB0 >> 2) & 1);
    const uint32_t offB4 = (uint32_t)(rB0*32 + hB4*16);

    float c[4][8][4];
    #pragma unroll
    for (int mt = 0; mt < 4; ++mt)
        #pragma unroll
        for (int nt = 0; nt < 8; ++nt)
            #pragma unroll
            for (int e = 0; e < 4; ++e) c[mt][nt][e] = 0.0f;

    // prologue: prefetch ktiles 0,1 into stages 0,1
    #pragma unroll
    for (int kt = 0; kt < 2; ++kt) {
        const uint32_t d = smbase + kt*ST3_B;
        const int off = kt*16;
        cp16(d + doffA, pa_h + off);
        cp16(d + O_ALO + doffA, pa_l + off);
        cp16(d + O_BHI + doffB0, pb_h0 + off);
        cp16(d + O_BHI + doffB1, pb_h1 + off);
        cp16(d + O_BLO + doffB0, pb_l0 + off);
        cp16(d + O_BLO + doffB1, pb_l1 + off);
        asm volatile("cp.async.commit_group;\n");
    }

    for (int kt = 0; kt < 32; ++kt) {
        const int p = kt & 1;
        asm volatile("cp.async.wait_group 1;\n");
        __syncthreads();

        const uint32_t sb = smbase + p*ST3_B;
        uint32_t ah[4][4], al[4][4], bh[8][2], bl[8][2];
        #pragma unroll
        for (int mt = 0; mt < 4; ++mt) ldsm4(ah[mt], sb + mt*512 + offA);
        #pragma unroll
        for (int mt = 0; mt < 4; ++mt) ldsm4(al[mt], sb + O_ALO + mt*512 + offA);
        #pragma unroll
        for (int np = 0; np < 4; ++np) {
            uint32_t btmp[4];
            ldsm4(btmp, sb + O_BHI + np*512 + offB4);
            bh[2*np][0] = btmp[0]; bh[2*np][1] = btmp[1];
            bh[2*np+1][0] = btmp[2]; bh[2*np+1][1] = btmp[3];
            ldsm4(btmp, sb + O_BLO + np*512 + offB4);
            bl[2*np][0] = btmp[0]; bl[2*np][1] = btmp[1];
            bl[2*np+1][0] = btmp[2]; bl[2*np+1][1] = btmp[3];
        }

        #pragma unroll
        for (int mt = 0; mt < 4; ++mt) {
            #pragma unroll
            for (int nt = 0; nt < 8; ++nt) {
                asm volatile(
                    "mma.sync.aligned.m16n8k16.row.col.f32.bf16.bf16.f32 "
                    "{%0,%1,%2,%3}, {%4,%5,%6,%7}, {%8,%9}, {%0,%1,%2,%3};"
                    : "+f"(c[mt][nt][0]), "+f"(c[mt][nt][1]),
                      "+f"(c[mt][nt][2]), "+f"(c[mt][nt][3])
                    : "r"(ah[mt][0]), "r"(ah[mt][1]), "r"(ah[mt][2]), "r"(ah[mt][3]),
                      "r"(bh[nt][0]), "r"(bh[nt][1]));
                asm volatile(
                    "mma.sync.aligned.m16n8k16.row.col.f32.bf16.bf16.f32 "
                    "{%0,%1,%2,%3}, {%4,%5,%6,%7}, {%8,%9}, {%0,%1,%2,%3};"
                    : "+f"(c[mt][nt][0]), "+f"(c[mt][nt][1]),
                      "+f"(c[mt][nt][2]), "+f"(c[mt][nt][3])
                    : "r"(al[mt][0]), "r"(al[mt][1]), "r"(al[mt][2]), "r"(al[mt][3]),
                      "r"(bh[nt][0]), "r"(bh[nt][1]));
                asm volatile(
                    "mma.sync.aligned.m16n8k16.row.col.f32.bf16.bf16.f32 "
                    "{%0,%1,%2,%3}, {%4,%5,%6,%7}, {%8,%9}, {%0,%1,%2,%3};"
                    : "+f"(c[mt][nt][0]), "+f"(c[mt][nt][1]),
                      "+f"(c[mt][nt][2]), "+f"(c[mt][nt][3])
                    : "r"(ah[mt][0]), "r"(ah[mt][1]), "r"(ah[mt][2]), "r"(ah[mt][3]),
                      "r"(bl[nt][0]), "r"(bl[nt][1]));
            }
        }

        __syncthreads();
        if (kt + 2 < 32) {
            const uint32_t d = smbase + p*ST3_B;
            const int off = (kt+2)*16;
            cp16(d + doffA, pa_h + off);
            cp16(d + O_ALO + doffA, pa_l + off);
            cp16(d + O_BHI + doffB0, pb_h0 + off);
            cp16(d + O_BHI + doffB1, pb_h1 + off);
            cp16(d + O_BLO + doffB0, pb_l0 + off);
            cp16(d + O_BLO + doffB1, pb_l1 + off);
        }
        asm volatile("cp.async.commit_group;\n");
    }

    // epilogue
    if (out_sel <= 2) {
        // head-major store: tile rows all in one batch b (TT = 18*128)
        const int b = bm / TT;
        #pragma unroll
        for (int mt = 0; mt < 4; ++mt) {
            const int rrow = bm + wm*64 + mt*16 + grp;
            const int t = rrow - b*TT;
            #pragma unroll
            for (int nt = 0; nt < 8; ++nt) {
                const int col = bn + wn*64 + nt*8 + qid*2;
                const int hh = col >> 3, n = col & 7;
                float* po = Out + hplane(dir, b, hh, t) + n;
                *(float2*)po            = make_float2(c[mt][nt][0], c[mt][nt][1]);
                *(float2*)(po + 8*NN)   = make_float2(c[mt][nt][2], c[mt][nt][3]);  // t+8
            }
        }
    } else {
        #pragma unroll
        for (int mt = 0; mt < 4; ++mt) {
            const int rrow = bm + wm*64 + mt*16 + grp;
            #pragma unroll
            for (int nt = 0; nt < 8; ++nt) {
                const int col = bn + wn*64 + nt*8 + qid*2;
                *(float2*)(Out + (size_t)rrow*CC + col)     = make_float2(c[mt][nt][0], c[mt][nt][1]);
                *(float2*)(Out + (size_t)(rrow+8)*CC + col) = make_float2(c[mt][nt][2], c[mt][nt][3]);
            }
        }
    }
}

// ---------------- WKV6 chunked scan (head-major operands, stride NN per step) ----------------
__global__ void wkv_pass1_kernel()
{
    const int gt = blockIdx.x*128 + threadIdx.x;
    const int s = gt & 15;
    const int j = s & 7, p = s >> 3;
    const int i0 = p*4;
    const int ucid = gt >> 4;
    const int cch = ucid % NCHUNK;
    const int unit = ucid / NCHUNK;
    const int h = unit & 63, b = (unit >> 6) & 7, dir = unit >> 9;

    const size_t base = hplane(dir, b, h, cch*CLEN);
    const float* kk = g_k + base;
    const float* vv = g_v + base;
    const float* dd = g_d + base;

    float S0=0.f,S1=0.f,S2=0.f,S3=0.f, P0=1.f,P1=1.f,P2=1.f,P3=1.f;
    int off = 0;
    #pragma unroll 4
    for (int t = 0; t < CLEN; ++t, off += NN) {
        const float4 k4 = ld4(kk + off + i0);
        const float4 d4 = ld4(dd + off + i0);
        const float v = vv[off + j];
        S0 = fmaf(d4.x, S0, k4.x*v); P0 *= d4.x;
        S1 = fmaf(d4.y, S1, k4.y*v); P1 *= d4.y;
        S2 = fmaf(d4.z, S2, k4.z*v); P2 *= d4.z;
        S3 = fmaf(d4.w, S3, k4.w*v); P3 *= d4.w;
    }
    float* Mp = g_M + (size_t)ucid*64;
    Mp[(i0+0)*8 + j] = S0;
    Mp[(i0+1)*8 + j] = S1;
    Mp[(i0+2)*8 + j] = S2;
    Mp[(i0+3)*8 + j] = S3;
    if (j == 0) {
        float* Pp = g_P + (size_t)ucid*8;
        Pp[i0+0] = P0; Pp[i0+1] = P1; Pp[i0+2] = P2; Pp[i0+3] = P3;
    }
}

__global__ void wkv_pass2_kernel()
{
    const int gt = blockIdx.x*128 + threadIdx.x;   // 16384 threads
    const int s = gt & 15;
    const int j = s & 7, p = s >> 3;
    const int i0 = p*4;
    const int unit = gt >> 4;

    float S0=0.f,S1=0.f,S2=0.f,S3=0.f;
    for (int cch = 0; cch < NCHUNK; ++cch) {
        const size_t uc = (size_t)unit*NCHUNK + cch;
        float* Sp = g_S0 + uc*64;
        Sp[(i0+0)*8 + j] = S0;
        Sp[(i0+1)*8 + j] = S1;
        Sp[(i0+2)*8 + j] = S2;
        Sp[(i0+3)*8 + j] = S3;
        const float* Pp = g_P + uc*8;
        const float* Mp = g_M + uc*64;
        S0 = fmaf(Pp[i0+0], S0, Mp[(i0+0)*8 + j]);
        S1 = fmaf(Pp[i0+1], S1, Mp[(i0+1)*8 + j]);
        S2 = fmaf(Pp[i0+2], S2, Mp[(i0+2)*8 + j]);
        S3 = fmaf(Pp[i0+3], S3, Mp[(i0+3)*8 + j]);
    }
}

__global__ void wkv_pass3_kernel(const float* __restrict__ u)
{
    const int gt = blockIdx.x*128 + threadIdx.x;
    const int s = gt & 15;
    const int j = s & 7, p = s >> 3;
    const int i0 = p*4;
    const int ucid = gt >> 4;
    const int cch = ucid % NCHUNK;
    const int unit = ucid / NCHUNK;
    const int h = unit & 63, b = (unit >> 6) & 7, dir = unit >> 9;

    const float4 uu = ld4(u + h*NN + i0);
    const size_t base = hplane(dir, b, h, cch*CLEN);
    const float* rr = g_r + base;
    const float* kk = g_k + base;
    const float* vv = g_v + base;
    const float* dd = g_d + base;
    float* yy = g_y + base;

    const float* Sp = g_S0 + (size_t)ucid*64;
    float S0 = Sp[(i0+0)*8 + j];
    float S1 = Sp[(i0+1)*8 + j];
    float S2 = Sp[(i0+2)*8 + j];
    float S3 = Sp[(i0+3)*8 + j];

    int off = 0;
    #pragma unroll 2
    for (int t = 0; t < CLEN; ++t, off += NN) {
        const float4 r4 = ld4(rr + off + i0);
        const float4 k4 = ld4(kk + off + i0);
        const float4 d4 = ld4(dd + off + i0);
        const float v = vv[off + j];
        float y = 0.f, kv, tt;
        kv = k4.x*v; tt = fmaf(uu.x, kv, S0); y = fmaf(r4.x, tt, y); S0 = fmaf(d4.x, S0, kv);
        kv = k4.y*v; tt = fmaf(uu.y, kv, S1); y = fmaf(r4.y, tt, y); S1 = fmaf(d4.y, S1, kv);
        kv = k4.z*v; tt = fmaf(uu.z, kv, S2); y = fmaf(r4.z, tt, y); S2 = fmaf(d4.z, S2, kv);
        kv = k4.w*v; tt = fmaf(uu.w, kv, S3); y = fmaf(r4.w, tt, y); S3 = fmaf(d4.w, S3, kv);
        y += __shfl_xor_sync(0xffffffffu, y, 8);
        if (p == 0) yy[off + j] = y;
    }
}

// ---------------- combine directions + layernorm -> bf16 hi/lo planes (slot 6) ----------------
__global__ void combine_ln_kernel(const float* __restrict__ lng,
                                  const float* __restrict__ lnb)
{
    const int t = blockIdx.x, b = blockIdx.y;
    const int tid = threadIdx.x;   // 128
    const int c0 = tid*4;
    const int hh = c0 >> 3, n0 = c0 & 7;   // n0 in {0,4}: float4 stays within head
    const int y = t / HS, xq = t % HS;
    const int tcol = xq*HS + y;
    const int m = b*TT + t;

    const float4 va = ld4(g_y + hplane(0, b, hh, t)    + n0);
    const float4 vb = ld4(g_y + hplane(1, b, hh, tcol) + n0);
    float4 o;
    o.x = 0.5f*(va.x + vb.x); o.y = 0.5f*(va.y + vb.y);
    o.z = 0.5f*(va.z + vb.z); o.w = 0.5f*(va.w + vb.w);
    float s  = o.x + o.y + o.z + o.w;
    float sq = o.x*o.x + o.y*o.y + o.z*o.z + o.w*o.w;
    #pragma unroll
    for (int off = 16; off > 0; off >>= 1) {
        s  += __shfl_xor_sync(0xffffffffu, s,  off);
        sq += __shfl_xor_sync(0xffffffffu, sq, off);
    }
    __shared__ float ss[4], sqs[4];
    if ((tid & 31) == 0) { ss[tid >> 5] = s; sqs[tid >> 5] = sq; }
    __syncthreads();
    s  = ss[0] + ss[1] + ss[2] + ss[3];
    sq = sqs[0] + sqs[1] + sqs[2] + sqs[3];
    const float mu = s * (1.0f/CC);
    const float var = sq * (1.0f/CC) - mu*mu;
    const float rstd = rsqrtf(var + 1e-5f);

    const float4 g4 = ld4(lng + c0);
    const float4 b4 = ld4(lnb + c0);
    float4 res;
    res.x = (o.x - mu)*rstd*g4.x + b4.x;
    res.y = (o.y - mu)*rstd*g4.y + b4.y;
    res.z = (o.z - mu)*rstd*g4.z + b4.z;
    res.w = (o.w - mu)*rstd*g4.w + b4.w;
    uint2 hi, lo;
    bfsplit4(res, hi, lo);
    const size_t u2idx = (size_t)m*128 + tid;
    ((uint2*)(g_Ahi + (size_t)6*BTC))[u2idx] = hi;
    ((uint2*)(g_Alo + (size_t)6*BTC))[u2idx] = lo;
}

// ---------------- launch ----------------
extern "C" void kernel_launch(void* const* d_in, const int* in_sizes, int n_in,
                              void* d_out, int out_size)
{
    (void)in_sizes; (void)n_in; (void)out_size;
    const float* x     = (const float*)d_in[0];
    const float* c1    = (const float*)d_in[3];
    const float* c3    = (const float*)d_in[4];
    const float* c5    = (const float*)d_in[5];
    const float* alpha = (const float*)d_in[6];
    const float* maa_w = (const float*)d_in[7];
    const float* maa_k = (const float*)d_in[8];
    const float* maa_v = (const float*)d_in[9];
    const float* maa_r = (const float*)d_in[10];
    const float* tdec  = (const float*)d_in[11];
    const float* w1    = (const float*)d_in[12];
    const float* w2    = (const float*)d_in[13];
    const float* uu    = (const float*)d_in[14];
    const float* Wr    = (const float*)d_in[15];
    const float* Wk    = (const float*)d_in[16];
    const float* Wv    = (const float*)d_in[17];
    const float* Wo    = (const float*)d_in[18];
    const float* lng   = (const float*)d_in[19];
    const float* lnb   = (const float*)d_in[20];

    prep_coef_kernel<<<1, 512>>>(c1, c3, c5, alpha);
    prep_w_kernel<<<(4*CC*CC/8)/256, 256>>>(Wr, Wk, Wv, Wo);
    conv_shift2_kernel<<<dim3(HS, BB, 2), 256>>>(x);
    fused_dp2_kernel<<<dim3(TT/TP, BB, 2), 256>>>(x, maa_w, maa_r, maa_k, maa_v, tdec, w1, w2);

    const dim3 ggrid(CC/256, MM/128);   // (2, 144)
    for (int dir = 0; dir < 2; ++dir) {
        gemm_bf16_kernel<<<ggrid, 256>>>(nullptr, dir*3+0, 0, 0, dir);
        gemm_bf16_kernel<<<ggrid, 256>>>(nullptr, dir*3+1, 1, 1, dir);
        gemm_bf16_kernel<<<ggrid, 256>>>(nullptr, dir*3+2, 2, 2, dir);
    }

    wkv_pass1_kernel<<<(NUNIT*NCHUNK*16)/128, 128>>>();
    wkv_pass2_kernel<<<(NUNIT*16)/128, 128>>>();
    wkv_pass3_kernel<<<(NUNIT*NCHUNK*16)/128, 128>>>(uu);

    combine_ln_kernel<<<dim3(TT, BB), 128>>>(lng, lnb);
    gemm_bf16_kernel<<<ggrid, 256>>>((float*)d_out, 6, 3, 3, 0);
}